// round 6
// baseline (speedup 1.0000x reference)
#include <cuda_runtime.h>
#include <cuda_bf16.h>
#include <math.h>

// ---------------- problem constants ----------------
#define Bn    2
#define Nn    2048
#define DIMn  512
#define Hn    4
#define DHn   128
#define CH    64
#define NCn   32
#define BHn   8
#define Pn    256            // BH * NC
#define DHIDn 512
#define ROWS  (Bn*Nn)        // 4096 tokens
#define KROWS (Pn*CH)        // 16384 chunk-major rows

// ---------------- static scratch (no cudaMalloc allowed) ----------------
__device__ float g_xs[ROWS*DIMn];
__device__ float g_xr[ROWS*DIMn];
__device__ float g_q [KROWS*DHn];
__device__ float g_k [KROWS*DHn];
__device__ float g_v [KROWS*DHn];
__device__ float g_u [KROWS*DHn];
__device__ float g_h [KROWS*DHn];
__device__ float g_hq[KROWS*DHn];
__device__ float g_lr[KROWS];
__device__ float g_gate[ROWS*Hn];
__device__ float g_beta [NCn*BHn];
__device__ float g_alpha[NCn*BHn];
__device__ float g_z1 [KROWS*DHIDn];
__device__ float g_a1 [KROWS*DHIDn];
__device__ float g_dz1[KROWS*DHIDn];
__device__ float g_dpred[KROWS*DHn];
__device__ float g_dh  [KROWS*DHn];
__device__ float g_gg [Pn*DHn];
__device__ float g_gw1[Pn*DHn*DHIDn];
__device__ float g_gw2[Pn*DHIDn*DHn];
__device__ float g_gp [Pn*DHn];
__device__ float g_w1p[(size_t)Pn*DHn*DHIDn];
__device__ float g_w2p[(size_t)Pn*DHIDn*DHn];
__device__ float g_ret[ROWS*DIMn];

// ---------------- small helpers ----------------
__device__ __forceinline__ float sigm(float x) { return 1.0f / (1.0f + expf(-x)); }
__device__ __forceinline__ float gelu_f(float x) {
    return 0.5f * x * (1.0f + erff(x * 0.70710678118654752f));
}
__device__ __forceinline__ float gelu_grad_f(float x) {
    float c = 0.5f * (1.0f + erff(x * 0.70710678118654752f));
    return c + x * 0.3989422804014327f * expf(-0.5f * x * x);
}

template<int NT>
__device__ __forceinline__ float blk_sum(float v) {
    __shared__ float sbuf[NT/32];
    int tid = threadIdx.x;
    #pragma unroll
    for (int o = 16; o > 0; o >>= 1) v += __shfl_xor_sync(0xffffffffu, v, o);
    if ((tid & 31) == 0) sbuf[tid >> 5] = v;
    __syncthreads();
    float s = (tid < NT/32) ? sbuf[tid] : 0.0f;
    if (tid < 32) {
        #pragma unroll
        for (int o = NT/64; o > 0; o >>= 1) s += __shfl_xor_sync(0xffffffffu, s, o);
        if (tid == 0) sbuf[0] = s;
    }
    __syncthreads();
    s = sbuf[0];
    __syncthreads();
    return s;
}

// ---------------- generic fp32 GEMM: C = op(A) @ op(B), optional batch, epilogue ----
// TA=0: A is [M,K] rowmajor. TA=1: A is [K,M] rowmajor (op(A)=A^T).
// TB=0: B is [K,N] rowmajor. TB=1: B is [N,K] rowmajor (op(B)=B^T).
#define GTILE 64
#define GBK   16

template<int TA, int TB, int EPI>
__global__ void __launch_bounds__(256)
gemm_k(const float* __restrict__ A, const float* __restrict__ B, float* __restrict__ C,
       int M, int N, int K, int lda, int ldb, int ldc,
       long sA, long sB, long sC)
{
    __shared__ float As[GTILE][GBK + 1];
    __shared__ float Bs[GBK][GTILE + 1];

    int p = blockIdx.z;
    A += (size_t)p * sA;
    B += (size_t)p * sB;
    C += (size_t)p * sC;

    int n0 = blockIdx.x * GTILE;
    int m0 = blockIdx.y * GTILE;
    int tid = threadIdx.x;
    int tx = tid & 15, ty = tid >> 4;

    float acc[4][4];
    #pragma unroll
    for (int i = 0; i < 4; i++)
        #pragma unroll
        for (int j = 0; j < 4; j++) acc[i][j] = 0.0f;

    for (int k0 = 0; k0 < K; k0 += GBK) {
        #pragma unroll
        for (int r = 0; r < 4; r++) {
            int idx = tid + r * 256;
            if (TA == 0) {
                int kk = idx & 15, mm = idx >> 4;
                As[mm][kk] = A[(size_t)(m0 + mm) * lda + (k0 + kk)];
            } else {
                int mm = idx & 63, kk = idx >> 6;
                As[mm][kk] = A[(size_t)(k0 + kk) * lda + (m0 + mm)];
            }
            if (TB == 0) {
                int nn = idx & 63, kk = idx >> 6;
                Bs[kk][nn] = B[(size_t)(k0 + kk) * ldb + (n0 + nn)];
            } else {
                int kk = idx & 15, nn = idx >> 4;
                Bs[kk][nn] = B[(size_t)(n0 + nn) * ldb + (k0 + kk)];
            }
        }
        __syncthreads();
        #pragma unroll
        for (int k = 0; k < GBK; k++) {
            float av[4], bv[4];
            #pragma unroll
            for (int i = 0; i < 4; i++) av[i] = As[ty + 16 * i][k];
            #pragma unroll
            for (int j = 0; j < 4; j++) bv[j] = Bs[k][tx + 16 * j];
            #pragma unroll
            for (int i = 0; i < 4; i++)
                #pragma unroll
                for (int j = 0; j < 4; j++) acc[i][j] += av[i] * bv[j];
        }
        __syncthreads();
    }

    #pragma unroll
    for (int i = 0; i < 4; i++) {
        int m = m0 + ty + 16 * i;
        #pragma unroll
        for (int j = 0; j < 4; j++) {
            int n = n0 + tx + 16 * j;
            float v = acc[i][j];
            if (EPI == 0) {                       // plain store
                C[(size_t)m * ldc + n] = v;
            } else if (EPI == 1) {                // qkv: remap token-major -> chunk-major
                int b = m >> 11, t = m & 2047, c = t >> 6, ii = t & 63;
                int h = n >> 7, d = n & 127;
                C[((size_t)((b * 4 + h) * 32 + c)) * (64 * 128) + ii * 128 + d] = v;
            } else if (EPI == 2) {                // z1 store + gelu -> g_a1
                size_t o = (size_t)m * 512 + n;
                C[o] = v;
                g_a1[o] = gelu_f(v);
            } else if (EPI == 3) {                // dpred = 2*lr/DH * (z2 + k - v)
                size_t o = (size_t)m * 128 + n;
                C[o] = (v + g_k[o] - g_v[o]) * g_lr[m] * (2.0f / 128.0f);
            } else if (EPI == 4) {                // dz1 = da1 * gelu'(z1)
                size_t o = (size_t)m * 512 + n;
                C[o] = v * gelu_grad_f(g_z1[o]);
            } else if (EPI == 5) {                // a1r = gelu(z1r)
                C[(size_t)m * ldc + n] = gelu_f(v);
            } else if (EPI == 6) {                // retrieved: (z2r + q) * gate -> token-major
                int pp = blockIdx.z;
                int bh = pp >> 5, c = pp & 31, b = bh >> 2, h = bh & 3;
                int t = c * 64 + m;
                float val = (v + g_q[((size_t)pp * 64 + m) * 128 + n]) *
                            g_gate[((size_t)(b * 2048 + t)) * 4 + h];
                g_ret[((size_t)(b * 2048 + t)) * 512 + h * 128 + n] = val;
            }
        }
    }
}

// ---------------- elementwise / reduction kernels ----------------

// per-token RMS norms -> g_xs, g_xr
__global__ void norms_kernel(const float* __restrict__ seq,
                             const float* __restrict__ gs,
                             const float* __restrict__ gr)
{
    int row = blockIdx.x;
    int tid = threadIdx.x;                       // 256
    const float* x = seq + (size_t)row * 512;
    float a = x[tid], b = x[tid + 256];
    float ss = blk_sum<256>(a * a + b * b);
    float r = rsqrtf(ss * (1.0f / 512.0f) + 1e-6f);
    g_xs[(size_t)row * 512 + tid]       = a * r * gs[tid];
    g_xs[(size_t)row * 512 + tid + 256] = b * r * gs[tid + 256];
    g_xr[(size_t)row * 512 + tid]       = a * r * gr[tid];
    g_xr[(size_t)row * 512 + tid + 256] = b * r * gr[tid + 256];
}

// pooled chunk stats -> beta, alpha
__global__ void pooled_gates_kernel(const float* __restrict__ Wm,
                                    const float* __restrict__ Wd,
                                    const float* __restrict__ bd)
{
    __shared__ float sm[512];
    int blk = blockIdx.x;                        // b*32 + c
    int b = blk >> 5, c = blk & 31;
    int tid = threadIdx.x;                       // 256
    const float* base = g_xs + ((size_t)(b * 2048 + c * 64)) * 512;
    float s0 = 0.0f, s1 = 0.0f;
    for (int i = 0; i < 64; i++) {
        s0 += base[(size_t)i * 512 + tid];
        s1 += base[(size_t)i * 512 + tid + 256];
    }
    sm[tid]       = s0 * (1.0f / 64.0f);
    sm[tid + 256] = s1 * (1.0f / 64.0f);
    __syncthreads();
    int w = tid >> 5, lane = tid & 31;
    if (w < 4) {
        float pm = 0.0f, pd = 0.0f;
        for (int d = lane; d < 512; d += 32) {
            float pv = sm[d];
            pm += pv * Wm[d * 4 + w];
            pd += pv * Wd[d * 4 + w];
        }
        #pragma unroll
        for (int o = 16; o > 0; o >>= 1) {
            pm += __shfl_xor_sync(0xffffffffu, pm, o);
            pd += __shfl_xor_sync(0xffffffffu, pd, o);
        }
        if (lane == 0) {
            g_beta [c * 8 + b * 4 + w] = sigm(pm);
            g_alpha[c * 8 + b * 4 + w] = 1.0f - sigm(pd + bd[w]);
        }
    }
}

// per-token lr (chunk-major) and retrieve gate (token-major)
__global__ void lrgate_kernel(const float* __restrict__ Wa,
                              const float* __restrict__ ba,
                              const float* __restrict__ Wg)
{
    int r = blockIdx.x;
    int tid = threadIdx.x;                       // 128
    int w = tid >> 5, lane = tid & 31;
    float pa = 0.0f, pg = 0.0f;
    for (int d = lane; d < 512; d += 32) {
        pa += g_xs[(size_t)r * 512 + d] * Wa[d * 4 + w];
        pg += g_xr[(size_t)r * 512 + d] * Wg[d * 4 + w];
    }
    #pragma unroll
    for (int o = 16; o > 0; o >>= 1) {
        pa += __shfl_xor_sync(0xffffffffu, pa, o);
        pg += __shfl_xor_sync(0xffffffffu, pg, o);
    }
    if (lane == 0) {
        int b = r >> 11, t = r & 2047, c = t >> 6, i = t & 63;
        g_lr[((size_t)((b * 4 + w) * 32 + c)) * 64 + i] = sigm(pa + ba[w]);
        g_gate[(size_t)r * 4 + w] = sigm(pg);
    }
}

// per-row RMS of k -> u, h = u * mem_g
__global__ void normk_kernel(const float* __restrict__ memg)
{
    int row = blockIdx.x;                        // 16384
    int d = threadIdx.x;                         // 128
    float x = g_k[(size_t)row * 128 + d];
    float ss = blk_sum<128>(x * x);
    float r = rsqrtf(ss * (1.0f / 128.0f) + 1e-6f);
    float u = x * r;
    g_u[(size_t)row * 128 + d] = u;
    g_h[(size_t)row * 128 + d] = u * memg[d];
}

// dg[p,d] = sum_i dh[p,i,d] * u[p,i,d]
__global__ void dg_kernel()
{
    int p = blockIdx.x;
    int d = threadIdx.x;
    float s = 0.0f;
    size_t base = (size_t)p * 64 * 128 + d;
    for (int i = 0; i < 64; i++)
        s += g_dh[base + (size_t)i * 128] * g_u[base + (size_t)i * 128];
    g_gg[(size_t)p * 128 + d] = s;
}

// momentum + decay scan over 32 chunks per weight element; writes w_prev per chunk
__global__ void scan_kernel(const float* __restrict__ memg,
                            const float* __restrict__ w1,
                            const float* __restrict__ w2)
{
    __shared__ float sb[NCn], sa[NCn];
    int tid = threadIdx.x;
    int bh = blockIdx.y;
    if (tid < NCn) {
        sb[tid] = g_beta [tid * BHn + bh];
        sa[tid] = g_alpha[tid * BHn + bh];
    }
    __syncthreads();
    const int E = DHn + DHn * DHIDn + DHIDn * DHn;   // 131200
    int e = blockIdx.x * blockDim.x + tid;
    if (e >= E) return;

    float w, m = 0.0f;
    const float* grad;
    float* wprev;
    size_t str;
    if (e < DHn) {
        w = memg[e];
        grad  = g_gg + (size_t)bh * 32 * 128 + e;
        wprev = g_gp + (size_t)bh * 32 * 128 + e;
        str = 128;
    } else if (e < DHn + DHn * DHIDn) {
        size_t o = e - DHn;
        w = w1[o];
        grad  = g_gw1 + (size_t)bh * 32 * 65536 + o;
        wprev = g_w1p + (size_t)bh * 32 * 65536 + o;
        str = 65536;
    } else {
        size_t o = e - DHn - DHn * DHIDn;
        w = w2[o];
        grad  = g_gw2 + (size_t)bh * 32 * 65536 + o;
        wprev = g_w2p + (size_t)bh * 32 * 65536 + o;
        str = 65536;
    }
    #pragma unroll 4
    for (int c = 0; c < NCn; c++) {
        wprev[(size_t)c * str] = w;                  // w_{c-1} seen by chunk c
        m = sb[c] * m - grad[(size_t)c * str];       // surprise = -grad
        w = sa[c] * w + m;
    }
}

// per-row RMS of q scaled by per-chunk g_prev -> hq
__global__ void hq_kernel()
{
    int row = blockIdx.x;                        // 16384
    int d = threadIdx.x;                         // 128
    int p = row >> 6;
    float x = g_q[(size_t)row * 128 + d];
    float ss = blk_sum<128>(x * x);
    float r = rsqrtf(ss * (1.0f / 128.0f) + 1e-6f);
    g_hq[(size_t)row * 128 + d] = x * r * g_gp[(size_t)p * 128 + d];
}

// ---------------- launch ----------------
extern "C" void kernel_launch(void* const* d_in, const int* in_sizes, int n_in,
                              void* d_out, int out_size)
{
    (void)in_sizes; (void)n_in; (void)out_size;
    const float* seq  = (const float*)d_in[0];
    const float* gsn  = (const float*)d_in[1];
    const float* grn  = (const float*)d_in[2];
    const float* Wq   = (const float*)d_in[3];
    const float* Wk   = (const float*)d_in[4];
    const float* Wv   = (const float*)d_in[5];
    const float* Wa   = (const float*)d_in[6];
    const float* ba   = (const float*)d_in[7];
    const float* Wm   = (const float*)d_in[8];
    const float* Wd   = (const float*)d_in[9];
    const float* bd   = (const float*)d_in[10];
    const float* Wg   = (const float*)d_in[11];
    const float* Wc   = (const float*)d_in[12];
    const float* memg = (const float*)d_in[13];
    const float* w1   = (const float*)d_in[14];
    const float* w2   = (const float*)d_in[15];
    float* out = (float*)d_out;

    float* pz1 = nullptr; float* pk = nullptr; float* pv = nullptr; float* pq = nullptr;
    float* pdp = nullptr; float* pdz = nullptr; float* pdh = nullptr;
    float* pgw1 = nullptr; float* pgw2 = nullptr; float* ph = nullptr; float* phq = nullptr;
    float* pa1 = nullptr; float* pw1p = nullptr; float* pw2p = nullptr; float* pret = nullptr;
    float* pxs = nullptr; float* pxr = nullptr;
    cudaGetSymbolAddress((void**)&pz1,  g_z1);
    cudaGetSymbolAddress((void**)&pk,   g_k);
    cudaGetSymbolAddress((void**)&pv,   g_v);
    cudaGetSymbolAddress((void**)&pq,   g_q);
    cudaGetSymbolAddress((void**)&pdp,  g_dpred);
    cudaGetSymbolAddress((void**)&pdz,  g_dz1);
    cudaGetSymbolAddress((void**)&pdh,  g_dh);
    cudaGetSymbolAddress((void**)&pgw1, g_gw1);
    cudaGetSymbolAddress((void**)&pgw2, g_gw2);
    cudaGetSymbolAddress((void**)&ph,   g_h);
    cudaGetSymbolAddress((void**)&phq,  g_hq);
    cudaGetSymbolAddress((void**)&pa1,  g_a1);
    cudaGetSymbolAddress((void**)&pw1p, g_w1p);
    cudaGetSymbolAddress((void**)&pw2p, g_w2p);
    cudaGetSymbolAddress((void**)&pret, g_ret);
    cudaGetSymbolAddress((void**)&pxs,  g_xs);
    cudaGetSymbolAddress((void**)&pxr,  g_xr);

    // 1. token norms
    norms_kernel<<<ROWS, 256>>>(seq, gsn, grn);

    // 2. pooled stats -> beta/alpha
    pooled_gates_kernel<<<Bn * NCn, 256>>>(Wm, Wd, bd);

    // 3. projections (remap to chunk-major)
    gemm_k<0,0,1><<<dim3(8, 64, 1), 256>>>(pxs, Wk, pk, ROWS, 512, 512, 512, 512, 0, 0, 0, 0);
    gemm_k<0,0,1><<<dim3(8, 64, 1), 256>>>(pxs, Wv, pv, ROWS, 512, 512, 512, 512, 0, 0, 0, 0);
    gemm_k<0,0,1><<<dim3(8, 64, 1), 256>>>(pxr, Wq, pq, ROWS, 512, 512, 512, 512, 0, 0, 0, 0);

    // 4. lr + gate
    lrgate_kernel<<<ROWS, 128>>>(Wa, ba, Wg);

    // 5. k-row RMS -> u, h
    normk_kernel<<<KROWS, 128>>>(memg);

    // 6. z1 = h @ w1 (+ gelu -> a1)
    gemm_k<0,0,2><<<dim3(8, 256, 1), 256>>>(ph, w1, pz1, KROWS, 512, 128, 128, 512, 512, 0, 0, 0);

    // 7. z2 = a1 @ w2 -> dpred (fused)
    gemm_k<0,0,3><<<dim3(2, 256, 1), 256>>>(pa1, w2, pdp, KROWS, 128, 512, 512, 128, 128, 0, 0, 0);

    // 8. dW2 = a1^T @ dpred (batched over 256 chunks)
    gemm_k<1,0,0><<<dim3(2, 8, Pn), 256>>>(pa1, pdp, pgw2, 512, 128, 64, 512, 128, 128,
                                           64L * 512, 64L * 128, 512L * 128);

    // 9. dz1 = (dpred @ w2^T) * gelu'(z1)
    gemm_k<0,1,4><<<dim3(8, 256, 1), 256>>>(pdp, w2, pdz, KROWS, 512, 128, 128, 128, 512, 0, 0, 0);

    // 10. dW1 = h^T @ dz1 (batched)
    gemm_k<1,0,0><<<dim3(8, 2, Pn), 256>>>(ph, pdz, pgw1, 128, 512, 64, 128, 512, 512,
                                           64L * 128, 64L * 512, 128L * 512);

    // 11. dh = dz1 @ w1^T
    gemm_k<0,1,0><<<dim3(2, 256, 1), 256>>>(pdz, w1, pdh, KROWS, 128, 512, 512, 512, 128, 0, 0, 0);

    // 12. dg reduction
    dg_kernel<<<Pn, 128>>>();

    // 13. momentum + decay scan, writes per-chunk w_prev
    {
        const int E = DHn + DHn * DHIDn + DHIDn * DHn;
        scan_kernel<<<dim3((E + 255) / 256, BHn), 256>>>(memg, w1, w2);
    }

    // 14. q-row RMS scaled by g_prev
    hq_kernel<<<KROWS, 128>>>();

    // 15. z1r = hq @ w1_prev (batched, gelu epilogue -> a1 reuse)
    gemm_k<0,0,5><<<dim3(8, 1, Pn), 256>>>(phq, pw1p, pa1, 64, 512, 128, 128, 512, 512,
                                           64L * 128, 128L * 512, 64L * 512);

    // 16. z2r = a1r @ w2_prev -> (.. + q) * gate, token-major
    gemm_k<0,0,6><<<dim3(2, 1, Pn), 256>>>(pa1, pw2p, pret, 64, 128, 512, 512, 128, 128,
                                           64L * 512, 512L * 128, 0);

    // 17. combine: out = ret @ Wc
    gemm_k<0,0,0><<<dim3(8, 64, 1), 256>>>(pret, Wc, out, ROWS, 512, 512, 512, 512, 512, 0, 0, 0);
}

// round 10
// speedup vs baseline: 1.0642x; 1.0642x over previous
#include <cuda_runtime.h>
#include <cuda_bf16.h>
#include <math.h>

// ---------------- problem constants ----------------
#define Bn    2
#define Nn    2048
#define DIMn  512
#define Hn    4
#define DHn   128
#define CH    64
#define NCn   32
#define BHn   8
#define Pn    256            // BH * NC
#define DHIDn 512
#define ROWS  (Bn*Nn)        // 4096 tokens
#define KROWS (Pn*CH)        // 16384 chunk-major rows

// ---------------- static scratch (no cudaMalloc allowed) ----------------
__device__ float g_xs[ROWS*DIMn];
__device__ float g_xr[ROWS*DIMn];
__device__ float g_q [KROWS*DHn];
__device__ float g_k [KROWS*DHn];
__device__ float g_v [KROWS*DHn];
__device__ float g_u [KROWS*DHn];
__device__ float g_h [KROWS*DHn];
__device__ float g_hq[KROWS*DHn];
__device__ float g_lr[KROWS];
__device__ float g_gate[ROWS*Hn];
__device__ float g_beta [NCn*BHn];
__device__ float g_alpha[NCn*BHn];
__device__ float g_z1 [KROWS*DHIDn];
__device__ float g_a1 [KROWS*DHIDn];
__device__ float g_dz1[KROWS*DHIDn];
__device__ float g_dpred[KROWS*DHn];
__device__ float g_dh  [KROWS*DHn];
__device__ float g_gg [Pn*DHn];
__device__ float g_gw1[Pn*DHn*DHIDn];
__device__ float g_gw2[Pn*DHIDn*DHn];
__device__ float g_gp [Pn*DHn];
__device__ float g_w1p[(size_t)Pn*DHn*DHIDn];
__device__ float g_w2p[(size_t)Pn*DHIDn*DHn];
__device__ float g_ret[ROWS*DIMn];

// ---------------- small helpers ----------------
__device__ __forceinline__ float sigm(float x) { return 1.0f / (1.0f + expf(-x)); }
__device__ __forceinline__ float gelu_f(float x) {
    return 0.5f * x * (1.0f + erff(x * 0.70710678118654752f));
}
__device__ __forceinline__ float gelu_grad_f(float x) {
    float c = 0.5f * (1.0f + erff(x * 0.70710678118654752f));
    return c + x * 0.3989422804014327f * expf(-0.5f * x * x);
}

__device__ __forceinline__ unsigned s2u(const void* p) {
    return (unsigned)__cvta_generic_to_shared(p);
}
__device__ __forceinline__ void cpa16(unsigned d, const void* s) {
    asm volatile("cp.async.cg.shared.global [%0], [%1], 16;" :: "r"(d), "l"(s));
}
__device__ __forceinline__ void cpa4(unsigned d, const void* s) {
    asm volatile("cp.async.ca.shared.global [%0], [%1], 4;" :: "r"(d), "l"(s));
}
#define CP_COMMIT() asm volatile("cp.async.commit_group;" ::: "memory")

template<int NT>
__device__ __forceinline__ float blk_sum(float v) {
    __shared__ float sbuf[NT/32];
    int tid = threadIdx.x;
    #pragma unroll
    for (int o = 16; o > 0; o >>= 1) v += __shfl_xor_sync(0xffffffffu, v, o);
    if ((tid & 31) == 0) sbuf[tid >> 5] = v;
    __syncthreads();
    float s = (tid < NT/32) ? sbuf[tid] : 0.0f;
    if (tid < 32) {
        #pragma unroll
        for (int o = NT/64; o > 0; o >>= 1) s += __shfl_xor_sync(0xffffffffu, s, o);
        if (tid == 0) sbuf[0] = s;
    }
    __syncthreads();
    s = sbuf[0];
    __syncthreads();
    return s;
}

// ---------------- FFMA2 GEMM: C = op(A) @ op(B), batched, fused epilogues ----
// Tile: TM x 128, BK=16, 256 threads (16x16), microtile (TM/16) x 8.
// TA=0: A [M,K] rowmajor. TA=1: A [K,M] rowmajor (op=A^T).
// TB=0: B [K,N] rowmajor. TB=1: B [N,K] rowmajor (op=B^T).
// Requires: M % TM == 0, N % 128 == 0, K % 16 == 0.
template<int TM, int TA, int TB, int EPI>
__global__ void __launch_bounds__(256, 2)
gemm2(const float* __restrict__ A, const float* __restrict__ B, float* __restrict__ C,
      int M, int N, int K, int lda, int ldb, int ldc,
      long sA, long sB, long sC)
{
    constexpr int MR = TM / 16;
    __shared__ __align__(16) float As[2][TM][20];     // row stride 80B (16B multiple)
    __shared__ __align__(16) float Bs[2][16][128];

    int p = blockIdx.z;
    A += (size_t)p * sA;
    B += (size_t)p * sB;
    C += (size_t)p * sC;

    int n0 = blockIdx.x * 128;
    int m0 = blockIdx.y * TM;
    int tid = threadIdx.x;
    int tx = tid & 15, ty = tid >> 4;

    auto stage = [&](int kt, int buf) {
        int k0 = kt * 16;
        if (TA == 0) {
            #pragma unroll
            for (int r = 0; r < TM/64; r++) {          // TM*4 16B chunks
                int e = tid + r * 256;
                int mm = e >> 2, kc = (e & 3) * 4;
                cpa16(s2u(&As[buf][mm][kc]), A + (size_t)(m0 + mm) * lda + (k0 + kc));
            }
        } else {
            #pragma unroll
            for (int r = 0; r < TM/16; r++) {          // TM*16 4B elems (transpose)
                int e = tid + r * 256;
                int mm = e % TM, kk = e / TM;
                cpa4(s2u(&As[buf][mm][kk]), A + (size_t)(k0 + kk) * lda + (m0 + mm));
            }
        }
        if (TB == 0) {
            #pragma unroll
            for (int r = 0; r < 2; r++) {              // 512 16B chunks
                int e = tid + r * 256;
                int kk = e >> 5, nc = (e & 31) * 4;
                cpa16(s2u(&Bs[buf][kk][nc]), B + (size_t)(k0 + kk) * ldb + (n0 + nc));
            }
        } else {
            #pragma unroll
            for (int r = 0; r < 8; r++) {              // 2048 4B elems (transpose)
                int e = tid + r * 256;
                int kk = e & 15, nn = e >> 4;
                cpa4(s2u(&Bs[buf][kk][nn]), B + (size_t)(n0 + nn) * ldb + (k0 + kk));
            }
        }
    };

    unsigned long long acc[MR][4];
    #pragma unroll
    for (int i = 0; i < MR; i++)
        #pragma unroll
        for (int j = 0; j < 4; j++) acc[i][j] = 0ull;

    int ktiles = K / 16;
    stage(0, 0); CP_COMMIT();

    for (int t = 0; t < ktiles; t++) {
        int cur = t & 1;
        if (t + 1 < ktiles) {
            stage(t + 1, cur ^ 1); CP_COMMIT();
            asm volatile("cp.async.wait_group 1;" ::: "memory");
        } else {
            asm volatile("cp.async.wait_group 0;" ::: "memory");
        }
        __syncthreads();
        #pragma unroll
        for (int k = 0; k < 16; k++) {
            unsigned long long bv[4];
            {
                ulonglong2 q0 = *reinterpret_cast<const ulonglong2*>(&Bs[cur][k][tx * 8]);
                ulonglong2 q1 = *reinterpret_cast<const ulonglong2*>(&Bs[cur][k][tx * 8 + 4]);
                bv[0] = q0.x; bv[1] = q0.y; bv[2] = q1.x; bv[3] = q1.y;
            }
            #pragma unroll
            for (int i = 0; i < MR; i++) {
                unsigned a = __float_as_uint(As[cur][ty * MR + i][k]);
                unsigned long long a2;
                asm("mov.b64 %0, {%1, %1};" : "=l"(a2) : "r"(a));
                #pragma unroll
                for (int jp = 0; jp < 4; jp++)
                    asm("fma.rn.f32x2 %0, %1, %2, %0;"
                        : "+l"(acc[i][jp]) : "l"(a2), "l"(bv[jp]));
            }
        }
        __syncthreads();
    }

    // epilogue: two float4 quads per row of the microtile
    #pragma unroll
    for (int i = 0; i < MR; i++) {
        int m = m0 + ty * MR + i;
        #pragma unroll
        for (int jq = 0; jq < 2; jq++) {
            int n = n0 + tx * 8 + jq * 4;
            float4 v;
            v.x = __uint_as_float((unsigned)(acc[i][2*jq]     & 0xffffffffull));
            v.y = __uint_as_float((unsigned)(acc[i][2*jq]    >> 32));
            v.z = __uint_as_float((unsigned)(acc[i][2*jq + 1] & 0xffffffffull));
            v.w = __uint_as_float((unsigned)(acc[i][2*jq + 1]>> 32));

            if (EPI == 0) {                      // plain
                *reinterpret_cast<float4*>(&C[(size_t)m * ldc + n]) = v;
            } else if (EPI == 1) {               // qkv remap token->chunk (quad stays in-head)
                int b = m >> 11, tt = m & 2047, c = tt >> 6, ii = tt & 63;
                int h = n >> 7, d = n & 127;
                size_t o = ((size_t)((b * 4 + h) * 32 + c)) * (64 * 128) + ii * 128 + d;
                *reinterpret_cast<float4*>(&C[o]) = v;
            } else if (EPI == 2) {               // z1 + gelu -> a1
                size_t o = (size_t)m * 512 + n;
                *reinterpret_cast<float4*>(&C[o]) = v;
                float4 g = make_float4(gelu_f(v.x), gelu_f(v.y), gelu_f(v.z), gelu_f(v.w));
                *reinterpret_cast<float4*>(&g_a1[o]) = g;
            } else if (EPI == 3) {               // dpred = 2*lr/DH * (z2 + k - v)
                size_t o = (size_t)m * 128 + n;
                float4 kk4 = *reinterpret_cast<const float4*>(&g_k[o]);
                float4 vv4 = *reinterpret_cast<const float4*>(&g_v[o]);
                float s = g_lr[m] * (2.0f / 128.0f);
                float4 r = make_float4((v.x + kk4.x - vv4.x) * s, (v.y + kk4.y - vv4.y) * s,
                                       (v.z + kk4.z - vv4.z) * s, (v.w + kk4.w - vv4.w) * s);
                *reinterpret_cast<float4*>(&C[o]) = r;
            } else if (EPI == 4) {               // dz1 = da1 * gelu'(z1)
                size_t o = (size_t)m * 512 + n;
                float4 z4 = *reinterpret_cast<const float4*>(&g_z1[o]);
                float4 r = make_float4(v.x * gelu_grad_f(z4.x), v.y * gelu_grad_f(z4.y),
                                       v.z * gelu_grad_f(z4.z), v.w * gelu_grad_f(z4.w));
                *reinterpret_cast<float4*>(&C[o]) = r;
            } else if (EPI == 5) {               // a1r = gelu(z1r)
                float4 g = make_float4(gelu_f(v.x), gelu_f(v.y), gelu_f(v.z), gelu_f(v.w));
                *reinterpret_cast<float4*>(&C[(size_t)m * ldc + n]) = g;
            } else if (EPI == 6) {               // (z2r + q) * gate -> token-major
                int pp = blockIdx.z;
                int bh = pp >> 5, c = pp & 31, b = bh >> 2, h = bh & 3;
                int tt = c * 64 + m;
                float4 q4 = *reinterpret_cast<const float4*>(&g_q[((size_t)pp * 64 + m) * 128 + n]);
                float gt = g_gate[((size_t)(b * 2048 + tt)) * 4 + h];
                float4 r = make_float4((v.x + q4.x) * gt, (v.y + q4.y) * gt,
                                       (v.z + q4.z) * gt, (v.w + q4.w) * gt);
                *reinterpret_cast<float4*>(&g_ret[((size_t)(b * 2048 + tt)) * 512 + h * 128 + n]) = r;
            }
        }
    }
}

// ---------------- elementwise / reduction kernels ----------------

__global__ void norms_kernel(const float* __restrict__ seq,
                             const float* __restrict__ gs,
                             const float* __restrict__ gr)
{
    int row = blockIdx.x;
    int tid = threadIdx.x;                       // 256
    const float* x = seq + (size_t)row * 512;
    float a = x[tid], b = x[tid + 256];
    float ss = blk_sum<256>(a * a + b * b);
    float r = rsqrtf(ss * (1.0f / 512.0f) + 1e-6f);
    g_xs[(size_t)row * 512 + tid]       = a * r * gs[tid];
    g_xs[(size_t)row * 512 + tid + 256] = b * r * gs[tid + 256];
    g_xr[(size_t)row * 512 + tid]       = a * r * gr[tid];
    g_xr[(size_t)row * 512 + tid + 256] = b * r * gr[tid + 256];
}

__global__ void pooled_gates_kernel(const float* __restrict__ Wm,
                                    const float* __restrict__ Wd,
                                    const float* __restrict__ bd)
{
    __shared__ float sm[512];
    int blk = blockIdx.x;                        // b*32 + c
    int b = blk >> 5, c = blk & 31;
    int tid = threadIdx.x;                       // 256
    const float* base = g_xs + ((size_t)(b * 2048 + c * 64)) * 512;
    float s0 = 0.0f, s1 = 0.0f;
    for (int i = 0; i < 64; i++) {
        s0 += base[(size_t)i * 512 + tid];
        s1 += base[(size_t)i * 512 + tid + 256];
    }
    sm[tid]       = s0 * (1.0f / 64.0f);
    sm[tid + 256] = s1 * (1.0f / 64.0f);
    __syncthreads();
    int w = tid >> 5, lane = tid & 31;
    if (w < 4) {
        float pm = 0.0f, pd = 0.0f;
        for (int d = lane; d < 512; d += 32) {
            float pv = sm[d];
            pm += pv * Wm[d * 4 + w];
            pd += pv * Wd[d * 4 + w];
        }
        #pragma unroll
        for (int o = 16; o > 0; o >>= 1) {
            pm += __shfl_xor_sync(0xffffffffu, pm, o);
            pd += __shfl_xor_sync(0xffffffffu, pd, o);
        }
        if (lane == 0) {
            g_beta [c * 8 + b * 4 + w] = sigm(pm);
            g_alpha[c * 8 + b * 4 + w] = 1.0f - sigm(pd + bd[w]);
        }
    }
}

__global__ void lrgate_kernel(const float* __restrict__ Wa,
                              const float* __restrict__ ba,
                              const float* __restrict__ Wg)
{
    int r = blockIdx.x;
    int tid = threadIdx.x;                       // 128
    int w = tid >> 5, lane = tid & 31;
    float pa = 0.0f, pg = 0.0f;
    for (int d = lane; d < 512; d += 32) {
        pa += g_xs[(size_t)r * 512 + d] * Wa[d * 4 + w];
        pg += g_xr[(size_t)r * 512 + d] * Wg[d * 4 + w];
    }
    #pragma unroll
    for (int o = 16; o > 0; o >>= 1) {
        pa += __shfl_xor_sync(0xffffffffu, pa, o);
        pg += __shfl_xor_sync(0xffffffffu, pg, o);
    }
    if (lane == 0) {
        int b = r >> 11, t = r & 2047, c = t >> 6, i = t & 63;
        g_lr[((size_t)((b * 4 + w) * 32 + c)) * 64 + i] = sigm(pa + ba[w]);
        g_gate[(size_t)r * 4 + w] = sigm(pg);
    }
}

__global__ void normk_kernel(const float* __restrict__ memg)
{
    int row = blockIdx.x;                        // 16384
    int d = threadIdx.x;                         // 128
    float x = g_k[(size_t)row * 128 + d];
    float ss = blk_sum<128>(x * x);
    float r = rsqrtf(ss * (1.0f / 128.0f) + 1e-6f);
    float u = x * r;
    g_u[(size_t)row * 128 + d] = u;
    g_h[(size_t)row * 128 + d] = u * memg[d];
}

__global__ void dg_kernel()
{
    int p = blockIdx.x;
    int d = threadIdx.x;
    float s = 0.0f;
    size_t base = (size_t)p * 64 * 128 + d;
    for (int i = 0; i < 64; i++)
        s += g_dh[base + (size_t)i * 128] * g_u[base + (size_t)i * 128];
    g_gg[(size_t)p * 128 + d] = s;
}

__global__ void scan_kernel(const float* __restrict__ memg,
                            const float* __restrict__ w1,
                            const float* __restrict__ w2)
{
    __shared__ float sb[NCn], sa[NCn];
    int tid = threadIdx.x;
    int bh = blockIdx.y;
    if (tid < NCn) {
        sb[tid] = g_beta [tid * BHn + bh];
        sa[tid] = g_alpha[tid * BHn + bh];
    }
    __syncthreads();
    const int E = DHn + DHn * DHIDn + DHIDn * DHn;   // 131200
    int e = blockIdx.x * blockDim.x + tid;
    if (e >= E) return;

    float w, m = 0.0f;
    const float* grad;
    float* wprev;
    size_t str;
    if (e < DHn) {
        w = memg[e];
        grad  = g_gg + (size_t)bh * 32 * 128 + e;
        wprev = g_gp + (size_t)bh * 32 * 128 + e;
        str = 128;
    } else if (e < DHn + DHn * DHIDn) {
        size_t o = e - DHn;
        w = w1[o];
        grad  = g_gw1 + (size_t)bh * 32 * 65536 + o;
        wprev = g_w1p + (size_t)bh * 32 * 65536 + o;
        str = 65536;
    } else {
        size_t o = e - DHn - DHn * DHIDn;
        w = w2[o];
        grad  = g_gw2 + (size_t)bh * 32 * 65536 + o;
        wprev = g_w2p + (size_t)bh * 32 * 65536 + o;
        str = 65536;
    }
    #pragma unroll 4
    for (int c = 0; c < NCn; c++) {
        wprev[(size_t)c * str] = w;                  // w_{c-1} seen by chunk c
        m = sb[c] * m - grad[(size_t)c * str];       // surprise = -grad
        w = sa[c] * w + m;
    }
}

__global__ void hq_kernel()
{
    int row = blockIdx.x;                        // 16384
    int d = threadIdx.x;                         // 128
    int p = row >> 6;
    float x = g_q[(size_t)row * 128 + d];
    float ss = blk_sum<128>(x * x);
    float r = rsqrtf(ss * (1.0f / 128.0f) + 1e-6f);
    g_hq[(size_t)row * 128 + d] = x * r * g_gp[(size_t)p * 128 + d];
}

// ---------------- launch ----------------
extern "C" void kernel_launch(void* const* d_in, const int* in_sizes, int n_in,
                              void* d_out, int out_size)
{
    (void)in_sizes; (void)n_in; (void)out_size;
    const float* seq  = (const float*)d_in[0];
    const float* gsn  = (const float*)d_in[1];
    const float* grn  = (const float*)d_in[2];
    const float* Wq   = (const float*)d_in[3];
    const float* Wk   = (const float*)d_in[4];
    const float* Wv   = (const float*)d_in[5];
    const float* Wa   = (const float*)d_in[6];
    const float* ba   = (const float*)d_in[7];
    const float* Wm   = (const float*)d_in[8];
    const float* Wd   = (const float*)d_in[9];
    const float* bd   = (const float*)d_in[10];
    const float* Wg   = (const float*)d_in[11];
    const float* Wc   = (const float*)d_in[12];
    const float* memg = (const float*)d_in[13];
    const float* w1   = (const float*)d_in[14];
    const float* w2   = (const float*)d_in[15];
    float* out = (float*)d_out;

    float* pz1 = nullptr; float* pk = nullptr; float* pv = nullptr; float* pq = nullptr;
    float* pdp = nullptr; float* pdz = nullptr; float* pdh = nullptr;
    float* pgw1 = nullptr; float* pgw2 = nullptr; float* ph = nullptr; float* phq = nullptr;
    float* pa1 = nullptr; float* pw1p = nullptr; float* pw2p = nullptr; float* pret = nullptr;
    float* pxs = nullptr; float* pxr = nullptr;
    cudaGetSymbolAddress((void**)&pz1,  g_z1);
    cudaGetSymbolAddress((void**)&pk,   g_k);
    cudaGetSymbolAddress((void**)&pv,   g_v);
    cudaGetSymbolAddress((void**)&pq,   g_q);
    cudaGetSymbolAddress((void**)&pdp,  g_dpred);
    cudaGetSymbolAddress((void**)&pdz,  g_dz1);
    cudaGetSymbolAddress((void**)&pdh,  g_dh);
    cudaGetSymbolAddress((void**)&pgw1, g_gw1);
    cudaGetSymbolAddress((void**)&pgw2, g_gw2);
    cudaGetSymbolAddress((void**)&ph,   g_h);
    cudaGetSymbolAddress((void**)&phq,  g_hq);
    cudaGetSymbolAddress((void**)&pa1,  g_a1);
    cudaGetSymbolAddress((void**)&pw1p, g_w1p);
    cudaGetSymbolAddress((void**)&pw2p, g_w2p);
    cudaGetSymbolAddress((void**)&pret, g_ret);
    cudaGetSymbolAddress((void**)&pxs,  g_xs);
    cudaGetSymbolAddress((void**)&pxr,  g_xr);

    // 1. token norms
    norms_kernel<<<ROWS, 256>>>(seq, gsn, grn);

    // 2. pooled stats -> beta/alpha
    pooled_gates_kernel<<<Bn * NCn, 256>>>(Wm, Wd, bd);

    // 3. projections (remap to chunk-major). TM=64 -> 256 blocks each.
    gemm2<64,0,0,1><<<dim3(4, 64, 1), 256>>>(pxs, Wk, pk, ROWS, 512, 512, 512, 512, 0, 0, 0, 0);
    gemm2<64,0,0,1><<<dim3(4, 64, 1), 256>>>(pxs, Wv, pv, ROWS, 512, 512, 512, 512, 0, 0, 0, 0);
    gemm2<64,0,0,1><<<dim3(4, 64, 1), 256>>>(pxr, Wq, pq, ROWS, 512, 512, 512, 512, 0, 0, 0, 0);

    // 4. lr + gate
    lrgate_kernel<<<ROWS, 128>>>(Wa, ba, Wg);

    // 5. k-row RMS -> u, h
    normk_kernel<<<KROWS, 128>>>(memg);

    // 6. z1 = h @ w1 (+ gelu -> a1)
    gemm2<128,0,0,2><<<dim3(4, 128, 1), 256>>>(ph, w1, pz1, KROWS, 512, 128, 128, 512, 512, 0, 0, 0);

    // 7. z2 = a1 @ w2 -> dpred (fused). N=128 -> TM=64 for 256 blocks.
    gemm2<64,0,0,3><<<dim3(1, 256, 1), 256>>>(pa1, w2, pdp, KROWS, 128, 512, 512, 128, 128, 0, 0, 0);

    // 8. dW2 = a1^T @ dpred (batched over 256 chunks)
    gemm2<128,1,0,0><<<dim3(1, 4, Pn), 256>>>(pa1, pdp, pgw2, 512, 128, 64, 512, 128, 128,
                                              64L * 512, 64L * 128, 512L * 128);

    // 9. dz1 = (dpred @ w2^T) * gelu'(z1)
    gemm2<128,0,1,4><<<dim3(4, 128, 1), 256>>>(pdp, w2, pdz, KROWS, 512, 128, 128, 128, 512, 0, 0, 0);

    // 10. dW1 = h^T @ dz1 (batched)
    gemm2<128,1,0,0><<<dim3(4, 1, Pn), 256>>>(ph, pdz, pgw1, 128, 512, 64, 128, 512, 512,
                                              64L * 128, 64L * 512, 128L * 512);

    // 11. dh = dz1 @ w1^T. N=128 -> TM=64.
    gemm2<64,0,1,0><<<dim3(1, 256, 1), 256>>>(pdz, w1, pdh, KROWS, 128, 512, 512, 512, 128, 0, 0, 0);

    // 12. dg reduction
    dg_kernel<<<Pn, 128>>>();

    // 13. momentum + decay scan, writes per-chunk w_prev
    {
        const int E = DHn + DHn * DHIDn + DHIDn * DHn;
        scan_kernel<<<dim3((E + 255) / 256, BHn), 256>>>(memg, w1, w2);
    }

    // 14. q-row RMS scaled by g_prev
    hq_kernel<<<KROWS, 128>>>();

    // 15. z1r = hq @ w1_prev (batched, gelu -> a1 reuse). M=64 per chunk.
    gemm2<64,0,0,5><<<dim3(4, 1, Pn), 256>>>(phq, pw1p, pa1, 64, 512, 128, 128, 512, 512,
                                             64L * 128, 128L * 512, 64L * 512);

    // 16. z2r = a1r @ w2_prev -> (.. + q) * gate, token-major
    gemm2<64,0,0,6><<<dim3(1, 1, Pn), 256>>>(pa1, pw2p, pret, 64, 128, 512, 512, 128, 128,
                                             64L * 512, 512L * 128, 0);

    // 17. combine: out = ret @ Wc
    gemm2<64,0,0,0><<<dim3(4, 64, 1), 256>>>(pret, Wc, out, ROWS, 512, 512, 512, 512, 512, 0, 0, 0);
}